// round 14
// baseline (speedup 1.0000x reference)
#include <cuda_runtime.h>
#include <cuda_fp16.h>
#include <math_constants.h>

// GAT autoencoder — single persistent kernel, grid-wide barriers.
// Layers: 64->64 relu, 64->32 [h out], relu, 32->64 relu, 64->64 [out].
// Outputs concatenated: out [N*64] then h [N*32].

#define MAXN 50000
#define MAXE 800000
#define MAXET (MAXE + MAXN)
#define STASH 80
#define NTH 512
#define NBLK 296  // 2 blocks/SM on 148 SMs; <=2/SM on 152 (GB300)

// ---------------- scratch ----------------
__device__ __align__(16) float g_featA[MAXN * 64];
__device__ __align__(16) float g_featB[MAXN * 64];
__device__ __align__(16) __half g_h[MAXN * 64];
__device__ float g_ssrc[MAXN];
__device__ float g_sdst[MAXN];
__device__ float g_e[MAXET];  // stash spill (deg > STASH), same-warp only
__device__ int g_src[MAXET];
__device__ int g_dst[MAXET];
__device__ int g_adj[MAXET];
__device__ int g_roff[MAXN + 1];
__device__ int g_cnt[MAXN];
__device__ int g_cur[MAXN];
__device__ int g_bt[64];
__device__ int g_boff[64];
__device__ unsigned int g_bar_count = 0;
__device__ volatile unsigned int g_bar_sense = 0;

struct KParams {
    const float* x;
    const void* ei;
    const float* W[4];
    const float* av[4];
    const float* dv[4];
    const float* b[4];
    float* out_sec;
    float* h_sec;
    int n, eraw;
};

// Sense-reversing grid barrier. Safe across graph replays: sense only flips
// when ALL blocks arrive, so the entry-time read of g_bar_sense is stable.
// __threadfence (gpu scope) on both sides: release + L1D invalidate.
__device__ __forceinline__ void gridbar(unsigned int* s_sense) {
    __syncthreads();
    if (threadIdx.x == 0) {
        unsigned int expect = *s_sense ^ 1u;
        __threadfence();
        unsigned int a = atomicAdd(&g_bar_count, 1u) + 1u;
        if (a == gridDim.x) {
            g_bar_count = 0u;
            __threadfence();
            g_bar_sense = expect;
        } else {
            while (g_bar_sense != expect) __nanosleep(64);
        }
        *s_sense = expect;
    }
    __syncthreads();
    __threadfence();
}

// ---------------- one GAT layer: gemm+scores, barrier, softmax-gather ----
template <int DI, int DO>
__device__ void do_layer(const float* __restrict__ xsrc,
                         const float* __restrict__ W,
                         const float* __restrict__ av,
                         const float* __restrict__ dv,
                         const float* __restrict__ bias,
                         float* feat, float* raw, int n,
                         float* Ws, float (*es)[STASH],
                         unsigned int* s_sense) {
    int tid = threadIdx.x, lane = tid & 31;
    for (int i = tid; i < DI * DO; i += NTH) Ws[i] = __ldg(&W[i]);
    __syncthreads();
    int gw = (blockIdx.x * NTH + tid) >> 5;
    int nwarp = (gridDim.x * NTH) >> 5;

    // ---- gemm + attention scores (warp per row) ----
    for (int row = gw; row < n; row += nwarp) {
        const float* x = xsrc + row * DI;
        float acc0 = 0.f, acc1 = 0.f;
#pragma unroll
        for (int k0 = 0; k0 < DI; k0 += 32) {
            float xv = __ldcg(&x[k0 + lane]);
#pragma unroll
            for (int kk = 0; kk < 32; kk++) {
                float xk = __shfl_sync(0xFFFFFFFFu, xv, kk);
                acc0 = fmaf(xk, Ws[(k0 + kk) * DO + lane], acc0);
                if (DO == 64) acc1 = fmaf(xk, Ws[(k0 + kk) * DO + lane + 32], acc1);
            }
        }
        g_h[row * DO + lane] = __float2half(acc0);
        if (DO == 64) g_h[row * DO + lane + 32] = __float2half(acc1);
        float ss = acc0 * __ldg(&av[lane]);
        float sd = acc0 * __ldg(&dv[lane]);
        if (DO == 64) {
            ss = fmaf(acc1, __ldg(&av[lane + 32]), ss);
            sd = fmaf(acc1, __ldg(&dv[lane + 32]), sd);
        }
#pragma unroll
        for (int off = 16; off; off >>= 1) {
            ss += __shfl_xor_sync(0xFFFFFFFFu, ss, off);
            sd += __shfl_xor_sync(0xFFFFFFFFu, sd, off);
        }
        if (lane == 0) {
            g_ssrc[row] = ss;
            g_sdst[row] = sd;
        }
    }
    gridbar(s_sense);

    // ---- softmax + aggregation (warp per node) ----
    const int C = DO / 16;
    int wslot = tid >> 5;
    int half = lane >> 4, l16 = lane & 15;
    for (int d = gw; d < n; d += nwarp) {
        int r0 = __ldg(&g_roff[d]);
        int r1 = __ldg(&g_roff[d + 1]);
        float sdl = __ldcg(&g_sdst[d]);
        float m = -CUDART_INF_F;
        for (int j = r0 + lane; j < r1; j += 32) {
            int s = __ldg(&g_adj[j]);
            float e = __ldcg(&g_ssrc[s]) + sdl;
            e = e > 0.f ? e : 0.2f * e;
            int k = j - r0;
            if (k < STASH) es[wslot][k] = e;
            else g_e[j] = e;
            m = fmaxf(m, e);
        }
#pragma unroll
        for (int off = 16; off; off >>= 1)
            m = fmaxf(m, __shfl_xor_sync(0xFFFFFFFFu, m, off));
        __syncwarp();

        float den = 0.f;
        float acc[C];
#pragma unroll
        for (int c = 0; c < C; c++) acc[c] = 0.f;
        for (int j = r0 + half; j < r1; j += 2) {
            int k = j - r0;
            float e = (k < STASH) ? es[wslot][k] : g_e[j];
            int s = __ldg(&g_adj[j]);
            float ex = __expf(e - m);
            den += ex;
            float hv[C];
            if (C == 4) {
                uint2 t = __ldcg(reinterpret_cast<const uint2*>(g_h + s * DO) + l16);
                float2 p0 = __half22float2(*reinterpret_cast<__half2*>(&t.x));
                float2 p1 = __half22float2(*reinterpret_cast<__half2*>(&t.y));
                hv[0] = p0.x; hv[1] = p0.y; hv[2] = p1.x; hv[3] = p1.y;
            } else {
                unsigned int t = __ldcg(reinterpret_cast<const unsigned int*>(g_h + s * DO) + l16);
                float2 p = __half22float2(*reinterpret_cast<__half2*>(&t));
                hv[0] = p.x; hv[1] = p.y;
            }
#pragma unroll
            for (int c = 0; c < C; c++) acc[c] = fmaf(ex, hv[c], acc[c]);
        }
        den += __shfl_xor_sync(0xFFFFFFFFu, den, 16);
#pragma unroll
        for (int c = 0; c < C; c++) acc[c] += __shfl_xor_sync(0xFFFFFFFFu, acc[c], 16);

        if (half == 0) {
            float inv = 1.f / (den + 1e-16f);
            float v[C];
#pragma unroll
            for (int c = 0; c < C; c++)
                v[c] = acc[c] * inv + __ldg(&bias[l16 * C + c]);
            if (raw) {
                if (C == 4)
                    reinterpret_cast<float4*>(raw + d * DO)[l16] =
                        make_float4(v[0], v[1], v[2], v[3]);
                else
                    reinterpret_cast<float2*>(raw + d * DO)[l16] =
                        make_float2(v[0], v[1]);
            }
            if (feat) {
#pragma unroll
                for (int c = 0; c < C; c++) v[c] = v[c] > 0.f ? v[c] : 0.f;
                if (C == 4)
                    reinterpret_cast<float4*>(feat + d * DO)[l16] =
                        make_float4(v[0], v[1], v[2], v[3]);
                else
                    reinterpret_cast<float2*>(feat + d * DO)[l16] =
                        make_float2(v[0], v[1]);
            }
        }
        __syncwarp();  // protect es reuse on next node
    }
}

// ---------------- the mega kernel ----------------
__global__ __launch_bounds__(NTH, 2) void k_mega(KParams p) {
    __shared__ float Ws[64 * 64];
    __shared__ float es[16][STASH];
    __shared__ int ws_i[16];
    __shared__ int s_flag;
    __shared__ unsigned int s_sense;

    int tid = threadIdx.x, lane = tid & 31, wid = tid >> 5;
    int gtid = blockIdx.x * NTH + tid;
    int gstride = gridDim.x * NTH;
    int n = p.n, eraw = p.eraw, etot = eraw + n;

    if (tid == 0) {
        s_sense = g_bar_sense;  // stable: can't flip until this block arrives
        s_flag = 0;
    }
    __syncthreads();

    // dtype detect (redundant per block) + zero cnt
    if (tid < 128) {
        unsigned int w = __ldg((const unsigned int*)p.ei + (2 * tid + 1));
        if (w) atomicOr(&s_flag, 1);
    }
    for (int i = gtid; i < n; i += gstride) g_cnt[i] = 0;
    __syncthreads();
    int is64 = !s_flag;
    gridbar(&s_sense);  // 1

    // convert + degree histogram
    for (int i = gtid; i < etot; i += gstride) {
        int s, d;
        if (i < eraw) {
            if (is64) {
                const long long* q = (const long long*)p.ei;
                s = (int)q[i];
                d = (int)q[eraw + i];
            } else {
                const int* q = (const int*)p.ei;
                s = q[i];
                d = q[eraw + i];
            }
            s = s < 0 ? 0 : (s >= n ? n - 1 : s);
            d = d < 0 ? 0 : (d >= n ? n - 1 : d);
        } else {
            s = d = i - eraw;
        }
        g_src[i] = s;
        g_dst[i] = d;
        atomicAdd(&g_cnt[d], 1);
    }
    gridbar(&s_sense);  // 2

    int nchunk = (n + 1023) / 1024;
    // chunk totals (block b handles chunk b)
    if (blockIdx.x < nchunk) {
        int i0 = blockIdx.x * 1024 + tid * 2;
        int t = 0;
        if (i0 < n) t += __ldcg(&g_cnt[i0]);
        if (i0 + 1 < n) t += __ldcg(&g_cnt[i0 + 1]);
#pragma unroll
        for (int off = 16; off; off >>= 1) t += __shfl_xor_sync(~0u, t, off);
        if (lane == 0) ws_i[wid] = t;
        __syncthreads();
        if (tid == 0) {
            int su = 0;
            for (int w2 = 0; w2 < 16; w2++) su += ws_i[w2];
            g_bt[blockIdx.x] = su;
        }
    }
    gridbar(&s_sense);  // 3

    // mid scan of chunk totals (block 0, warp 0)
    if (blockIdx.x == 0 && wid == 0) {
        int carry = 0;
        for (int base = 0; base < nchunk; base += 32) {
            int i = base + lane;
            int v = (i < nchunk) ? __ldcg(&g_bt[i]) : 0;
            int incl = v;
#pragma unroll
            for (int off = 1; off < 32; off <<= 1) {
                int t = __shfl_up_sync(~0u, incl, off);
                if (lane >= off) incl += t;
            }
            if (i < nchunk) g_boff[i] = carry + incl - v;
            carry += __shfl_sync(~0u, incl, 31);
        }
        if (lane == 0) g_roff[n] = carry;
    }
    gridbar(&s_sense);  // 4

    // per-chunk exclusive offsets
    if (blockIdx.x < nchunk) {
        int i0 = blockIdx.x * 1024 + tid * 2;
        int v0 = (i0 < n) ? __ldcg(&g_cnt[i0]) : 0;
        int v1 = (i0 + 1 < n) ? __ldcg(&g_cnt[i0 + 1]) : 0;
        int tsum = v0 + v1;
        int incl = tsum;
#pragma unroll
        for (int off = 1; off < 32; off <<= 1) {
            int t = __shfl_up_sync(~0u, incl, off);
            if (lane >= off) incl += t;
        }
        if (lane == 31) ws_i[wid] = incl;
        __syncthreads();
        int woff = 0;
        for (int w2 = 0; w2 < wid; w2++) woff += ws_i[w2];
        int ex = __ldcg(&g_boff[blockIdx.x]) + woff + incl - tsum;
        if (i0 < n) { g_roff[i0] = ex; g_cur[i0] = ex; }
        if (i0 + 1 < n) { g_roff[i0 + 1] = ex + v0; g_cur[i0 + 1] = ex + v0; }
    }
    gridbar(&s_sense);  // 5

    // scatter adjacency
    for (int i = gtid; i < etot; i += gstride) {
        int d = __ldcg(&g_dst[i]);
        int pos = atomicAdd(&g_cur[d], 1);
        g_adj[pos] = __ldcg(&g_src[i]);
    }
    gridbar(&s_sense);  // 6

    // 4 layers (each has one internal barrier between gemm and gather)
    do_layer<64, 64>(p.x, p.W[0], p.av[0], p.dv[0], p.b[0], g_featA, nullptr, n, Ws, es, &s_sense);
    gridbar(&s_sense);
    do_layer<64, 32>(g_featA, p.W[1], p.av[1], p.dv[1], p.b[1], g_featB, p.h_sec, n, Ws, es, &s_sense);
    gridbar(&s_sense);
    do_layer<32, 64>(g_featB, p.W[2], p.av[2], p.dv[2], p.b[2], g_featA, nullptr, n, Ws, es, &s_sense);
    gridbar(&s_sense);
    do_layer<64, 64>(g_featA, p.W[3], p.av[3], p.dv[3], p.b[3], nullptr, p.out_sec, n, Ws, es, &s_sense);
}

// ---------------- launch ----------------
extern "C" void kernel_launch(void* const* d_in, const int* in_sizes, int n_in,
                              void* d_out, int out_size) {
    KParams p;
    p.x = (const float*)d_in[0];
    p.ei = d_in[1];
    for (int l = 0; l < 4; l++) {
        p.W[l] = (const float*)d_in[2 + 4 * l];
        p.av[l] = (const float*)d_in[3 + 4 * l];
        p.dv[l] = (const float*)d_in[4 + 4 * l];
        p.b[l] = (const float*)d_in[5 + 4 * l];
    }
    p.n = in_sizes[0] / 64;
    p.eraw = in_sizes[1] / 2;
    p.out_sec = (float*)d_out;
    p.h_sec = (float*)d_out + p.n * 64;

    k_mega<<<NBLK, NTH>>>(p);
}

// round 16
// speedup vs baseline: 1.1063x; 1.1063x over previous
#include <cuda_runtime.h>
#include <cuda_fp16.h>
#include <math_constants.h>

// GAT autoencoder, CSR-gather, single-pass softmax via per-layer global
// score upper bound (leaky-relu is monotone => lrelu(Smax+sdst) bounds all
// node logits). h stored fp16 (gather operand only).
// Layers: 64->64 relu, 64->32 [h out], relu, 32->64 relu, 64->64 [out].
// Outputs concatenated: out [N*64] then h [N*32].

#define MAXN 50000
#define MAXE 800000
#define MAXET (MAXE + MAXN)
#define MAXBLK 64

// ---------------- scratch ----------------
__device__ __align__(16) float g_featA[MAXN * 64];
__device__ __align__(16) float g_featB[MAXN * 64];
__device__ __align__(16) __half g_h[MAXN * 64];
__device__ float g_ssrc[MAXN];
__device__ float g_sdst[MAXN];
__device__ int g_src[MAXET];
__device__ int g_dst[MAXET];
__device__ int g_adj[MAXET];
__device__ int g_roff[MAXN + 1];
__device__ int g_cnt[MAXN];
__device__ int g_cur[MAXN];
__device__ int g_bt[MAXBLK];
__device__ int g_boff[MAXBLK];
__device__ int g_smax[4 * 32];  // per-layer spread max slots (float bits)
__device__ int g_is64;

__device__ __forceinline__ const float* pick_src(int sel, const float* ext) {
    if (sel == 1) return g_featA;
    if (sel == 2) return g_featB;
    return ext;
}
__device__ __forceinline__ float* pick_dst(int sel) {
    if (sel == 1) return g_featA;
    if (sel == 2) return g_featB;
    return nullptr;
}

// ---------------- graph prep ----------------

__global__ void k_detect(const unsigned int* __restrict__ w, int nelem) {
    __shared__ int bad;
    if (threadIdx.x == 0) bad = 0;
    __syncthreads();
    int idx = 2 * (int)threadIdx.x + 1;
    if (idx < 2 * nelem && idx < 256 && w[idx] != 0) atomicOr(&bad, 1);
    __syncthreads();
    if (threadIdx.x == 0) g_is64 = !bad;
}

__global__ void k_zero(int n) {
    int i = blockIdx.x * 256 + threadIdx.x;
    if (i < n) g_cnt[i] = 0;
    if (i < 4 * 32) g_smax[i] = (int)0xFF800000;  // -inf
}

// convert + degree histogram fused
__global__ void k_convert(const void* __restrict__ ei, int eraw, int n) {
    int i = blockIdx.x * 256 + threadIdx.x;
    int etot = eraw + n;
    if (i >= etot) return;
    int s, d;
    if (i < eraw) {
        if (g_is64) {
            const long long* p = (const long long*)ei;
            s = (int)p[i];
            d = (int)p[eraw + i];
        } else {
            const int* p = (const int*)ei;
            s = p[i];
            d = p[eraw + i];
        }
        s = s < 0 ? 0 : (s >= n ? n - 1 : s);
        d = d < 0 ? 0 : (d >= n ? n - 1 : d);
    } else {
        s = d = i - eraw;
    }
    g_src[i] = s;
    g_dst[i] = d;
    atomicAdd(&g_cnt[d], 1);
}

// --- two-level exclusive scan of g_cnt ---
__global__ void k_scan_bt(int n) {
    int base = blockIdx.x * 1024;
    int i0 = base + threadIdx.x * 4;
    int t = 0;
#pragma unroll
    for (int c = 0; c < 4; c++) t += (i0 + c < n) ? g_cnt[i0 + c] : 0;
    int lane = threadIdx.x & 31, wid = threadIdx.x >> 5;
#pragma unroll
    for (int off = 16; off; off >>= 1) t += __shfl_xor_sync(~0u, t, off);
    __shared__ int ws[8];
    if (lane == 0) ws[wid] = t;
    __syncthreads();
    if (threadIdx.x == 0) {
        int s = 0;
#pragma unroll
        for (int w = 0; w < 8; w++) s += ws[w];
        g_bt[blockIdx.x] = s;
    }
}

__global__ void k_scan_mid(int nblk, int n) {
    int lane = threadIdx.x;
    int carry = 0;
    for (int base = 0; base < nblk; base += 32) {
        int i = base + lane;
        int v = (i < nblk) ? g_bt[i] : 0;
        int incl = v;
#pragma unroll
        for (int off = 1; off < 32; off <<= 1) {
            int t = __shfl_up_sync(~0u, incl, off);
            if (lane >= off) incl += t;
        }
        if (i < nblk) g_boff[i] = carry + incl - v;
        carry += __shfl_sync(~0u, incl, 31);
    }
    if (lane == 0) g_roff[n] = carry;
}

__global__ void k_scan_wr(int n) {
    int base = blockIdx.x * 1024;
    int i0 = base + threadIdx.x * 4;
    int v[4], tsum = 0;
#pragma unroll
    for (int c = 0; c < 4; c++) {
        v[c] = (i0 + c < n) ? g_cnt[i0 + c] : 0;
        tsum += v[c];
    }
    int lane = threadIdx.x & 31, wid = threadIdx.x >> 5;
    int incl = tsum;
#pragma unroll
    for (int off = 1; off < 32; off <<= 1) {
        int t = __shfl_up_sync(~0u, incl, off);
        if (lane >= off) incl += t;
    }
    __shared__ int ws[8];
    if (lane == 31) ws[wid] = incl;
    __syncthreads();
    int woff = 0;
    for (int w = 0; w < wid; w++) woff += ws[w];
    int ex = g_boff[blockIdx.x] + woff + incl - tsum;
#pragma unroll
    for (int c = 0; c < 4; c++) {
        if (i0 + c < n) {
            g_roff[i0 + c] = ex;
            g_cur[i0 + c] = ex;
            ex += v[c];
        }
    }
}

__global__ void k_scatter(int etot) {
    int i = blockIdx.x * 256 + threadIdx.x;
    if (i >= etot) return;
    int pos = atomicAdd(&g_cur[g_dst[i]], 1);
    g_adj[pos] = g_src[i];
}

// ---------------- fused gemm + scores + global score max ----------------
template <int DI, int DO>
__global__ void k_gemm_sc(int xsel, const float* __restrict__ xext,
                          const float* __restrict__ W,
                          const float* __restrict__ as_,
                          const float* __restrict__ ad_, int n, int li) {
    __shared__ float Ws[DI * DO];
    __shared__ float s_ss[16];
    for (int i = threadIdx.x; i < DI * DO; i += blockDim.x) Ws[i] = W[i];
    __syncthreads();
    int wid = threadIdx.x >> 5;
    int row0 = (blockIdx.x * blockDim.x + threadIdx.x) >> 5;
    int lane = threadIdx.x & 31;
    bool valid = row0 < n;
    int row = valid ? row0 : n - 1;
    const float* x = pick_src(xsel, xext) + row * DI;
    float acc0 = 0.f, acc1 = 0.f;
#pragma unroll
    for (int k0 = 0; k0 < DI; k0 += 32) {
        float xv = x[k0 + lane];
#pragma unroll
        for (int kk = 0; kk < 32; kk++) {
            float xk = __shfl_sync(0xFFFFFFFFu, xv, kk);
            acc0 = fmaf(xk, Ws[(k0 + kk) * DO + lane], acc0);
            if (DO == 64) acc1 = fmaf(xk, Ws[(k0 + kk) * DO + lane + 32], acc1);
        }
    }
    if (valid) {
        g_h[row * DO + lane] = __float2half(acc0);
        if (DO == 64) g_h[row * DO + lane + 32] = __float2half(acc1);
    }
    float ss = acc0 * __ldg(as_ + lane);
    float sd = acc0 * __ldg(ad_ + lane);
    if (DO == 64) {
        ss = fmaf(acc1, __ldg(as_ + lane + 32), ss);
        sd = fmaf(acc1, __ldg(ad_ + lane + 32), sd);
    }
#pragma unroll
    for (int off = 16; off; off >>= 1) {
        ss += __shfl_xor_sync(0xFFFFFFFFu, ss, off);
        sd += __shfl_xor_sync(0xFFFFFFFFu, sd, off);
    }
    if (lane == 0) {
        if (valid) {
            g_ssrc[row] = ss;
            g_sdst[row] = sd;
        }
        s_ss[wid] = valid ? ss : -CUDART_INF_F;
    }
    __syncthreads();
    if (threadIdx.x == 0) {
        float mx = s_ss[0];
#pragma unroll
        for (int w = 1; w < 16; w++) mx = fmaxf(mx, s_ss[w]);
        int* p = &g_smax[li * 32 + (blockIdx.x & 31)];
        if (mx >= 0.f)
            atomicMax(p, __float_as_int(mx));
        else
            atomicMin((unsigned int*)p, __float_as_uint(mx));
    }
}

// ---------------- single-pass softmax + aggregation ----------------
// warp per dst node; m = lrelu(Smax_global + sdst) >= all node logits.
// Two half-warps process alternating edges; ssrc[s] is a 16-lane broadcast.
template <int DO>
__global__ void k_gather(const float* __restrict__ b, int featsel,
                         float* __restrict__ raw, int n, int li) {
    const int C = DO / 16;  // 4 (DO=64) or 2 (DO=32) cols per lane
    int d = (blockIdx.x * blockDim.x + threadIdx.x) >> 5;
    int lane = threadIdx.x & 31;
    int half = lane >> 4, l16 = lane & 15;
    if (d >= n) return;

    // per-layer global score max (32 spread slots, warp reduce)
    float sm = __int_as_float(g_smax[li * 32 + lane]);
#pragma unroll
    for (int off = 16; off; off >>= 1)
        sm = fmaxf(sm, __shfl_xor_sync(0xFFFFFFFFu, sm, off));

    int r0 = __ldg(&g_roff[d]);
    int r1 = __ldg(&g_roff[d + 1]);
    float sd = g_sdst[d];
    float m = sm + sd;
    m = m > 0.f ? m : 0.2f * m;  // lrelu monotone => m >= all node logits

    float den = 0.f;
    float acc[C];
#pragma unroll
    for (int c = 0; c < C; c++) acc[c] = 0.f;
    for (int j = r0 + half; j < r1; j += 2) {
        int s = __ldg(&g_adj[j]);
        float e = g_ssrc[s] + sd;  // broadcast within half-warp
        e = e > 0.f ? e : 0.2f * e;
        float ex = __expf(e - m);
        den += ex;
        float hv[C];
        if (C == 4) {
            uint2 t = __ldg(reinterpret_cast<const uint2*>(g_h + s * DO) + l16);
            float2 p0 = __half22float2(*reinterpret_cast<__half2*>(&t.x));
            float2 p1 = __half22float2(*reinterpret_cast<__half2*>(&t.y));
            hv[0] = p0.x; hv[1] = p0.y; hv[2] = p1.x; hv[3] = p1.y;
        } else {
            unsigned int t = __ldg(reinterpret_cast<const unsigned int*>(g_h + s * DO) + l16);
            float2 p = __half22float2(*reinterpret_cast<__half2*>(&t));
            hv[0] = p.x; hv[1] = p.y;
        }
#pragma unroll
        for (int c = 0; c < C; c++) acc[c] = fmaf(ex, hv[c], acc[c]);
    }
    // merge the two halves
    den += __shfl_xor_sync(0xFFFFFFFFu, den, 16);
#pragma unroll
    for (int c = 0; c < C; c++) acc[c] += __shfl_xor_sync(0xFFFFFFFFu, acc[c], 16);

    if (half == 0) {
        float inv = 1.f / (den + 1e-16f);
        float v[C];
#pragma unroll
        for (int c = 0; c < C; c++)
            v[c] = acc[c] * inv + __ldg(b + l16 * C + c);
        float* feat = pick_dst(featsel);
        if (raw) {
            if (C == 4)
                reinterpret_cast<float4*>(raw + d * DO)[l16] =
                    make_float4(v[0], v[1], v[2], v[3]);
            else
                reinterpret_cast<float2*>(raw + d * DO)[l16] =
                    make_float2(v[0], v[1]);
        }
        if (feat) {
#pragma unroll
            for (int c = 0; c < C; c++) v[c] = v[c] > 0.f ? v[c] : 0.f;
            if (C == 4)
                reinterpret_cast<float4*>(feat + d * DO)[l16] =
                    make_float4(v[0], v[1], v[2], v[3]);
            else
                reinterpret_cast<float2*>(feat + d * DO)[l16] =
                    make_float2(v[0], v[1]);
        }
    }
}

// ---------------- launch ----------------
extern "C" void kernel_launch(void* const* d_in, const int* in_sizes, int n_in,
                              void* d_out, int out_size) {
    const float* x = (const float*)d_in[0];
    const void* ei = d_in[1];
    const float* w1 = (const float*)d_in[2];
    const float* as1 = (const float*)d_in[3];
    const float* ad1 = (const float*)d_in[4];
    const float* b1 = (const float*)d_in[5];
    const float* w2 = (const float*)d_in[6];
    const float* as2 = (const float*)d_in[7];
    const float* ad2 = (const float*)d_in[8];
    const float* b2 = (const float*)d_in[9];
    const float* w3 = (const float*)d_in[10];
    const float* as3 = (const float*)d_in[11];
    const float* ad3 = (const float*)d_in[12];
    const float* b3 = (const float*)d_in[13];
    const float* w4 = (const float*)d_in[14];
    const float* as4 = (const float*)d_in[15];
    const float* ad4 = (const float*)d_in[16];
    const float* b4 = (const float*)d_in[17];

    int n = in_sizes[0] / 64;
    int eraw = in_sizes[1] / 2;
    int etot = eraw + n;

    float* out_sec = (float*)d_out;         // [n*64]
    float* h_sec = (float*)d_out + n * 64;  // [n*32]

    int nbE = (etot + 255) / 256;
    int nbN = (n + 255) / 256;
    int nbW = (n * 32 + 511) / 512;
    int nblk = (n + 1023) / 1024;

    // graph prep (once per call)
    k_detect<<<1, 128>>>((const unsigned int*)ei, in_sizes[1]);
    k_zero<<<nbN, 256>>>(n);
    k_convert<<<nbE, 256>>>(ei, eraw, n);
    k_scan_bt<<<nblk, 256>>>(n);
    k_scan_mid<<<1, 32>>>(nblk, n);
    k_scan_wr<<<nblk, 256>>>(n);
    k_scatter<<<nbE, 256>>>(etot);

    // layer 1: x 64->64, relu -> featA
    k_gemm_sc<64, 64><<<nbW, 512>>>(0, x, w1, as1, ad1, n, 0);
    k_gather<64><<<nbW, 512>>>(b1, 1, nullptr, n, 0);

    // layer 2: featA 64->32, raw h -> d_out, relu -> featB
    k_gemm_sc<64, 32><<<nbW, 512>>>(1, nullptr, w2, as2, ad2, n, 1);
    k_gather<32><<<nbW, 512>>>(b2, 2, h_sec, n, 1);

    // layer 3: featB 32->64, relu -> featA
    k_gemm_sc<32, 64><<<nbW, 512>>>(2, nullptr, w3, as3, ad3, n, 2);
    k_gather<64><<<nbW, 512>>>(b3, 1, nullptr, n, 2);

    // layer 4: featA 64->64, raw -> d_out
    k_gemm_sc<64, 64><<<nbW, 512>>>(1, nullptr, w4, as4, ad4, n, 3);
    k_gather<64><<<nbW, 512>>>(b4, 0, out_sec, n, 3);
}

// round 17
// speedup vs baseline: 1.2006x; 1.0853x over previous
#include <cuda_runtime.h>
#include <cuda_fp16.h>
#include <math_constants.h>

// GAT autoencoder. CSR gather, single-pass softmax (per-layer global score
// bound), fp16 h, and gather->next-gemm fusion with ping-pong h buffers.
// Layers: 64->64 relu, 64->32 [h out], relu, 32->64 relu, 64->64 [out].
// Outputs concatenated: out [N*64] then h [N*32].

#define MAXN 50000
#define MAXE 800000
#define MAXET (MAXE + MAXN)
#define MAXBLK 64

// ---------------- scratch ----------------
__device__ __align__(16) __half g_hA[MAXN * 64];
__device__ __align__(16) __half g_hB[MAXN * 64];
__device__ float g_ssrcA[MAXN];
__device__ float g_ssrcB[MAXN];
__device__ float g_sdstA[MAXN];
__device__ float g_sdstB[MAXN];
__device__ int g_src[MAXET];
__device__ int g_dst[MAXET];
__device__ int g_adj[MAXET];
__device__ int g_roff[MAXN + 1];
__device__ int g_cnt[MAXN];
__device__ int g_cur[MAXN];
__device__ int g_bt[MAXBLK];
__device__ int g_boff[MAXBLK];
__device__ int g_smax[4 * 32];  // per-layer spread max slots (float bits)
__device__ int g_is64;

__device__ __forceinline__ const __half* hR(int p) { return p ? g_hB : g_hA; }
__device__ __forceinline__ __half* hW(int p) { return p ? g_hB : g_hA; }
__device__ __forceinline__ const float* ssR(int p) { return p ? g_ssrcB : g_ssrcA; }
__device__ __forceinline__ float* ssW(int p) { return p ? g_ssrcB : g_ssrcA; }
__device__ __forceinline__ const float* sdR(int p) { return p ? g_sdstB : g_sdstA; }
__device__ __forceinline__ float* sdW(int p) { return p ? g_sdstB : g_sdstA; }

// ---------------- graph prep ----------------

__global__ void k_detect(const unsigned int* __restrict__ w, int nelem) {
    __shared__ int bad;
    if (threadIdx.x == 0) bad = 0;
    __syncthreads();
    int idx = 2 * (int)threadIdx.x + 1;
    if (idx < 2 * nelem && idx < 256 && w[idx] != 0) atomicOr(&bad, 1);
    __syncthreads();
    if (threadIdx.x == 0) g_is64 = !bad;
}

__global__ void k_zero(int n) {
    int i = blockIdx.x * 256 + threadIdx.x;
    if (i < n) g_cnt[i] = 0;
    if (i < 4 * 32) g_smax[i] = (int)0xFF800000;  // -inf
}

// convert + degree histogram fused
__global__ void k_convert(const void* __restrict__ ei, int eraw, int n) {
    int i = blockIdx.x * 256 + threadIdx.x;
    int etot = eraw + n;
    if (i >= etot) return;
    int s, d;
    if (i < eraw) {
        if (g_is64) {
            const long long* p = (const long long*)ei;
            s = (int)p[i];
            d = (int)p[eraw + i];
        } else {
            const int* p = (const int*)ei;
            s = p[i];
            d = p[eraw + i];
        }
        s = s < 0 ? 0 : (s >= n ? n - 1 : s);
        d = d < 0 ? 0 : (d >= n ? n - 1 : d);
    } else {
        s = d = i - eraw;
    }
    g_src[i] = s;
    g_dst[i] = d;
    atomicAdd(&g_cnt[d], 1);
}

// --- two-level exclusive scan of g_cnt ---
__global__ void k_scan_bt(int n) {
    int base = blockIdx.x * 1024;
    int i0 = base + threadIdx.x * 4;
    int t = 0;
#pragma unroll
    for (int c = 0; c < 4; c++) t += (i0 + c < n) ? g_cnt[i0 + c] : 0;
    int lane = threadIdx.x & 31, wid = threadIdx.x >> 5;
#pragma unroll
    for (int off = 16; off; off >>= 1) t += __shfl_xor_sync(~0u, t, off);
    __shared__ int ws[8];
    if (lane == 0) ws[wid] = t;
    __syncthreads();
    if (threadIdx.x == 0) {
        int s = 0;
#pragma unroll
        for (int w = 0; w < 8; w++) s += ws[w];
        g_bt[blockIdx.x] = s;
    }
}

__global__ void k_scan_mid(int nblk, int n) {
    int lane = threadIdx.x;
    int carry = 0;
    for (int base = 0; base < nblk; base += 32) {
        int i = base + lane;
        int v = (i < nblk) ? g_bt[i] : 0;
        int incl = v;
#pragma unroll
        for (int off = 1; off < 32; off <<= 1) {
            int t = __shfl_up_sync(~0u, incl, off);
            if (lane >= off) incl += t;
        }
        if (i < nblk) g_boff[i] = carry + incl - v;
        carry += __shfl_sync(~0u, incl, 31);
    }
    if (lane == 0) g_roff[n] = carry;
}

__global__ void k_scan_wr(int n) {
    int base = blockIdx.x * 1024;
    int i0 = base + threadIdx.x * 4;
    int v[4], tsum = 0;
#pragma unroll
    for (int c = 0; c < 4; c++) {
        v[c] = (i0 + c < n) ? g_cnt[i0 + c] : 0;
        tsum += v[c];
    }
    int lane = threadIdx.x & 31, wid = threadIdx.x >> 5;
    int incl = tsum;
#pragma unroll
    for (int off = 1; off < 32; off <<= 1) {
        int t = __shfl_up_sync(~0u, incl, off);
        if (lane >= off) incl += t;
    }
    __shared__ int ws[8];
    if (lane == 31) ws[wid] = incl;
    __syncthreads();
    int woff = 0;
    for (int w = 0; w < wid; w++) woff += ws[w];
    int ex = g_boff[blockIdx.x] + woff + incl - tsum;
#pragma unroll
    for (int c = 0; c < 4; c++) {
        if (i0 + c < n) {
            g_roff[i0 + c] = ex;
            g_cur[i0 + c] = ex;
            ex += v[c];
        }
    }
}

__global__ void k_scatter(int etot) {
    int i = blockIdx.x * 256 + threadIdx.x;
    if (i >= etot) return;
    int pos = atomicAdd(&g_cur[g_dst[i]], 1);
    g_adj[pos] = g_src[i];
}

// ---------------- layer-1 gemm + scores + global score max -> A bufs ----
__global__ void k_gemm1(const float* __restrict__ xext,
                        const float* __restrict__ W,
                        const float* __restrict__ as_,
                        const float* __restrict__ ad_, int n) {
    const int DI = 64, DO = 64;
    __shared__ float Ws[DI * DO];
    __shared__ float s_ss[16];
    for (int i = threadIdx.x; i < DI * DO; i += blockDim.x) Ws[i] = W[i];
    __syncthreads();
    int wid = threadIdx.x >> 5;
    int row0 = (blockIdx.x * blockDim.x + threadIdx.x) >> 5;
    int lane = threadIdx.x & 31;
    bool valid = row0 < n;
    int row = valid ? row0 : n - 1;
    const float* x = xext + row * DI;
    float acc0 = 0.f, acc1 = 0.f;
#pragma unroll
    for (int k0 = 0; k0 < DI; k0 += 32) {
        float xv = x[k0 + lane];
#pragma unroll
        for (int kk = 0; kk < 32; kk++) {
            float xk = __shfl_sync(0xFFFFFFFFu, xv, kk);
            acc0 = fmaf(xk, Ws[(k0 + kk) * DO + lane], acc0);
            acc1 = fmaf(xk, Ws[(k0 + kk) * DO + lane + 32], acc1);
        }
    }
    if (valid) {
        g_hA[row * DO + lane] = __float2half(acc0);
        g_hA[row * DO + lane + 32] = __float2half(acc1);
    }
    float ss = acc0 * __ldg(as_ + lane) + acc1 * __ldg(as_ + lane + 32);
    float sd = acc0 * __ldg(ad_ + lane) + acc1 * __ldg(ad_ + lane + 32);
#pragma unroll
    for (int off = 16; off; off >>= 1) {
        ss += __shfl_xor_sync(0xFFFFFFFFu, ss, off);
        sd += __shfl_xor_sync(0xFFFFFFFFu, sd, off);
    }
    if (lane == 0) {
        if (valid) {
            g_ssrcA[row] = ss;
            g_sdstA[row] = sd;
        }
        s_ss[wid] = valid ? ss : -CUDART_INF_F;
    }
    __syncthreads();
    if (threadIdx.x == 0) {
        float mx = s_ss[0];
#pragma unroll
        for (int w = 1; w < 16; w++) mx = fmaxf(mx, s_ss[w]);
        int* p = &g_smax[0 * 32 + (blockIdx.x & 31)];
        if (mx >= 0.f) atomicMax(p, __float_as_int(mx));
        else atomicMin((unsigned int*)p, __float_as_uint(mx));
    }
}

// -------- gather core: single-pass softmax aggregation for node d --------
// Returns v[Cp] (post-bias, pre-relu), identical on all lanes' (l16) cols.
template <int DOp>
__device__ __forceinline__ void gather_node(
    int d, int prevsel, int li_prev, const float* __restrict__ bias,
    int lane, int half, int l16, float* v) {
    const int Cp = DOp / 16;
    float sm = __int_as_float(g_smax[li_prev * 32 + lane]);
#pragma unroll
    for (int off = 16; off; off >>= 1)
        sm = fmaxf(sm, __shfl_xor_sync(0xFFFFFFFFu, sm, off));
    int r0 = __ldg(&g_roff[d]);
    int r1 = __ldg(&g_roff[d + 1]);
    const float* ssrcp = ssR(prevsel);
    const __half* hp = hR(prevsel);
    float sd = sdR(prevsel)[d];
    float m = sm + sd;
    m = m > 0.f ? m : 0.2f * m;

    float den = 0.f;
    float acc[Cp];
#pragma unroll
    for (int c = 0; c < Cp; c++) acc[c] = 0.f;
    for (int j = r0 + half; j < r1; j += 2) {
        int s = __ldg(&g_adj[j]);
        float e = ssrcp[s] + sd;
        e = e > 0.f ? e : 0.2f * e;
        float ex = __expf(e - m);
        den += ex;
        float hv[Cp];
        if (Cp == 4) {
            uint2 t = __ldg(reinterpret_cast<const uint2*>(hp + s * DOp) + l16);
            float2 p0 = __half22float2(*reinterpret_cast<__half2*>(&t.x));
            float2 p1 = __half22float2(*reinterpret_cast<__half2*>(&t.y));
            hv[0] = p0.x; hv[1] = p0.y; hv[2] = p1.x; hv[3] = p1.y;
        } else {
            unsigned int t = __ldg(reinterpret_cast<const unsigned int*>(hp + s * DOp) + l16);
            float2 p = __half22float2(*reinterpret_cast<__half2*>(&t));
            hv[0] = p.x; hv[1] = p.y;
        }
#pragma unroll
        for (int c = 0; c < Cp; c++) acc[c] = fmaf(ex, hv[c], acc[c]);
    }
    den += __shfl_xor_sync(0xFFFFFFFFu, den, 16);
#pragma unroll
    for (int c = 0; c < Cp; c++) acc[c] += __shfl_xor_sync(0xFFFFFFFFu, acc[c], 16);
    float inv = 1.f / (den + 1e-16f);
#pragma unroll
    for (int c = 0; c < Cp; c++) v[c] = acc[c] * inv + __ldg(bias + l16 * Cp + c);
}

// -------- fused: gather layer L (prevsel) -> gemm layer L+1 (nextsel) ----
template <int DOp, int DOn>
__global__ void k_fused(int prevsel, int li_prev,
                        const float* __restrict__ bias_prev,
                        float* __restrict__ raw_prev,
                        const float* __restrict__ W,
                        const float* __restrict__ as_,
                        const float* __restrict__ ad_, int n) {
    const int Cp = DOp / 16;
    __shared__ float Ws[DOp * DOn];
    __shared__ float s_ss[16];
    for (int i = threadIdx.x; i < DOp * DOn; i += blockDim.x) Ws[i] = W[i];
    __syncthreads();
    int wid = threadIdx.x >> 5;
    int lane = threadIdx.x & 31;
    int half = lane >> 4, l16 = lane & 15;
    int d0 = (blockIdx.x * blockDim.x + threadIdx.x) >> 5;
    bool valid = d0 < n;
    int d = valid ? d0 : n - 1;
    int nextsel = prevsel ^ 1;

    float v[Cp];
    gather_node<DOp>(d, prevsel, li_prev, bias_prev, lane, half, l16, v);

    if (valid && raw_prev && half == 0) {
        if (Cp == 4)
            reinterpret_cast<float4*>(raw_prev + d * DOp)[l16] =
                make_float4(v[0], v[1], v[2], v[3]);
        else
            reinterpret_cast<float2*>(raw_prev + d * DOp)[l16] =
                make_float2(v[0], v[1]);
    }
    // relu -> next layer input (register-resident, lanes 0-15 hold the row)
#pragma unroll
    for (int c = 0; c < Cp; c++) v[c] = v[c] > 0.f ? v[c] : 0.f;

    // gemm: DI = DOp via shfl from lanes 0-15; DO = DOn cols per lane
    float acc0 = 0.f, acc1 = 0.f;
#pragma unroll
    for (int k = 0; k < DOp; k++) {
        float xk = __shfl_sync(0xFFFFFFFFu, v[k & (Cp - 1)], k / Cp);
        acc0 = fmaf(xk, Ws[k * DOn + lane], acc0);
        if (DOn == 64) acc1 = fmaf(xk, Ws[k * DOn + lane + 32], acc1);
    }
    if (valid) {
        __half* hn = hW(nextsel);
        hn[d * DOn + lane] = __float2half(acc0);
        if (DOn == 64) hn[d * DOn + lane + 32] = __float2half(acc1);
    }
    float ss = acc0 * __ldg(as_ + lane);
    float sd2 = acc0 * __ldg(ad_ + lane);
    if (DOn == 64) {
        ss = fmaf(acc1, __ldg(as_ + lane + 32), ss);
        sd2 = fmaf(acc1, __ldg(ad_ + lane + 32), sd2);
    }
#pragma unroll
    for (int off = 16; off; off >>= 1) {
        ss += __shfl_xor_sync(0xFFFFFFFFu, ss, off);
        sd2 += __shfl_xor_sync(0xFFFFFFFFu, sd2, off);
    }
    if (lane == 0) {
        if (valid) {
            ssW(nextsel)[d] = ss;
            sdW(nextsel)[d] = sd2;
        }
        s_ss[wid] = valid ? ss : -CUDART_INF_F;
    }
    __syncthreads();
    if (threadIdx.x == 0) {
        float mx = s_ss[0];
#pragma unroll
        for (int w = 1; w < 16; w++) mx = fmaxf(mx, s_ss[w]);
        int* p = &g_smax[(li_prev + 1) * 32 + (blockIdx.x & 31)];
        if (mx >= 0.f) atomicMax(p, __float_as_int(mx));
        else atomicMin((unsigned int*)p, __float_as_uint(mx));
    }
}

// -------- final gather (layer 4): writes out only --------
__global__ void k_gather_fin(int prevsel, int li_prev,
                             const float* __restrict__ bias,
                             float* __restrict__ raw, int n) {
    int d = (blockIdx.x * blockDim.x + threadIdx.x) >> 5;
    int lane = threadIdx.x & 31;
    int half = lane >> 4, l16 = lane & 15;
    if (d >= n) return;
    float v[4];
    gather_node<64>(d, prevsel, li_prev, bias, lane, half, l16, v);
    if (half == 0)
        reinterpret_cast<float4*>(raw + d * 64)[l16] =
            make_float4(v[0], v[1], v[2], v[3]);
}

// ---------------- launch ----------------
extern "C" void kernel_launch(void* const* d_in, const int* in_sizes, int n_in,
                              void* d_out, int out_size) {
    const float* x = (const float*)d_in[0];
    const void* ei = d_in[1];
    const float* w1 = (const float*)d_in[2];
    const float* as1 = (const float*)d_in[3];
    const float* ad1 = (const float*)d_in[4];
    const float* b1 = (const float*)d_in[5];
    const float* w2 = (const float*)d_in[6];
    const float* as2 = (const float*)d_in[7];
    const float* ad2 = (const float*)d_in[8];
    const float* b2 = (const float*)d_in[9];
    const float* w3 = (const float*)d_in[10];
    const float* as3 = (const float*)d_in[11];
    const float* ad3 = (const float*)d_in[12];
    const float* b3 = (const float*)d_in[13];
    const float* w4 = (const float*)d_in[14];
    const float* as4 = (const float*)d_in[15];
    const float* ad4 = (const float*)d_in[16];
    const float* b4 = (const float*)d_in[17];

    int n = in_sizes[0] / 64;
    int eraw = in_sizes[1] / 2;
    int etot = eraw + n;

    float* out_sec = (float*)d_out;         // [n*64]
    float* h_sec = (float*)d_out + n * 64;  // [n*32]

    int nbE = (etot + 255) / 256;
    int nbN = (n + 255) / 256;
    int nbW = (n * 32 + 511) / 512;
    int nblk = (n + 1023) / 1024;

    // graph prep
    k_detect<<<1, 128>>>((const unsigned int*)ei, in_sizes[1]);
    k_zero<<<nbN, 256>>>(n);
    k_convert<<<nbE, 256>>>(ei, eraw, n);
    k_scan_bt<<<nblk, 256>>>(n);
    k_scan_mid<<<1, 32>>>(nblk, n);
    k_scan_wr<<<nblk, 256>>>(n);
    k_scatter<<<nbE, 256>>>(etot);

    // layer 1 gemm -> A
    k_gemm1<<<nbW, 512>>>(x, w1, as1, ad1, n);
    // gather1(A) + gemm2 -> B
    k_fused<64, 32><<<nbW, 512>>>(0, 0, b1, nullptr, w2, as2, ad2, n);
    // gather2(B) [raw h] + gemm3 -> A
    k_fused<32, 64><<<nbW, 512>>>(1, 1, b2, h_sec, w3, as3, ad3, n);
    // gather3(A) + gemm4 -> B
    k_fused<64, 64><<<nbW, 512>>>(0, 2, b3, nullptr, w4, as4, ad4, n);
    // gather4(B) -> out
    k_gather_fin<<<nbW, 512>>>(1, 3, b4, out_sec, n);
}